// round 14
// baseline (speedup 1.0000x reference)
#include <cuda_runtime.h>
#include <math.h>

#define RP 32
#define RR 8
#define NB 8
#define NPT 32768
#define PI_F 3.14159265358979323846f

// ---------------- scratch (device globals; no allocation allowed) ----------------
__device__ float g_ft[NB * RR * RP * RP];     // (b, r, theta, phi) -- zeroed at tail
__device__ float g_h1[NB * 32 * RP * RP];     // conv1 out
__device__ float g_h2[NB * 64 * RP * RP];     // conv2 out
__device__ float g_ftmax[NB * 64];
__device__ float g_Bvec[NB * 64];
__device__ float g_wq[RP];
__device__ float g_wc1[8 * 9 * 32];           // conv1 weights, [ic*9+k9][oc]
__device__ float g_wc2[32 * 9 * 64];          // conv2 weights, [ic*9+k9][oc]
__device__ float g_w1t[64 * 64];              // W1 head transposed: [c][d] (plain)
__device__ float g_w2t[64 * 32];              // W2 head transposed: [d][e]

// ---------------- f32x2 packed helpers ------------------------------------------
__device__ __forceinline__ unsigned long long ffma2(unsigned long long a,
                                                    unsigned long long b,
                                                    unsigned long long c) {
    unsigned long long d;
    asm("fma.rn.f32x2 %0, %1, %2, %3;" : "=l"(d) : "l"(a), "l"(b), "l"(c));
    return d;
}
__device__ __forceinline__ unsigned long long pack2(float lo, float hi) {
    unsigned long long d;
    asm("mov.b64 %0, {%1, %2};" : "=l"(d) : "f"(lo), "f"(hi));
    return d;
}
__device__ __forceinline__ void unpack2(unsigned long long v, float& lo, float& hi) {
    asm("mov.b64 {%0, %1}, %2;" : "=f"(lo), "=f"(hi) : "l"(v));
}

// ---------------- init: quadrature weights + weight re-layouts (NO grid zero) ----
__global__ void k_init(const float* __restrict__ Wc1, const float* __restrict__ Wc2,
                       const float* __restrict__ W1h, const float* __restrict__ W2h) {
    int i = blockIdx.x * blockDim.x + threadIdx.x;   // 72 * 256 = 18432 threads
    if (i < RP) {
        double jj = (double)i;
        double theta = M_PI * (2.0 * jj + 1.0) / 64.0;
        double s = 0.0;
        for (int k = 0; k < 16; k++)
            s += sin((2.0 * jj + 1.0) * (2.0 * k + 1.0) * M_PI / 64.0) / (2.0 * k + 1.0);
        g_wq[i] = (float)((2.0 / 16.0) * sin(theta) * s);
    }
    if (i < 8 * 9 * 32) {                            // conv1 weights transpose
        int ic9 = i >> 5, oc = i & 31;
        g_wc1[i] = Wc1[oc * 72 + ic9];
    }
    if (i < 32 * 9 * 64) {                           // conv2 weights transpose
        int ic9 = i >> 6, oc = i & 63;
        g_wc2[i] = Wc2[oc * 288 + ic9];
    }
    if (i < 4096) {                                  // head W1 transpose [c][d] (plain)
        int c = i >> 6, d = i & 63;
        g_w1t[i] = W1h[d * 128 + c];
    }
    if (i < 2048) {                                  // head W2 transpose: [d][e]
        int d = i >> 5, e = i & 31;
        g_w2t[i] = W2h[e * 64 + d];
    }
}

// ---------------- scatter: gaussian splat of w into (b, r, t, p) grid ------------
// g_ft arrives zeroed: static zero-init on first call, k_ftg re-zeroes at tail.
__global__ void __launch_bounds__(256) k_scatter(const float* __restrict__ pts,
                          const float* __restrict__ scp, const float* __restrict__ sgp,
                          const float* __restrict__ Ap, const float* __restrict__ icp) {
    int i = blockIdx.x * blockDim.x + threadIdx.x;
    if (i >= NB * NPT) return;
    float scale = *scp, sigma = *sgp, A = *Ap, icc = *icp;
    float x = pts[i * 3 + 0], y = pts[i * 3 + 1], z = pts[i * 3 + 2];
    float r = fmaxf(sqrtf(x * x + y * y + z * z), 0.1f);
    float th = acosf(fminf(fmaxf(__fdividef(z, r), -1.f), 1.f));
    float ph = atan2f(y, x) + PI_F;
    float ct = th * (float)(RP / M_PI);
    float cp = ph * (float)(RP / (2.0 * M_PI));
    float cr = __fdividef(r, scale) * (float)RR;
    int it = min(max((int)floorf(ct), 0), RP - 1);
    int ip = min(max((int)floorf(cp), 0), RP - 1);
    int ir = min(max((int)floorf(cr), 0), RR - 1);
    float dt = ct - ((float)it + icc);
    float dp = cp - ((float)ip + icc);
    float dr = cr - ((float)ir + icc);
    float d2 = dt * dt + dp * dp + dr * dr;
    float w = A * __expf(-d2 * __fdividef(0.5f, sigma * sigma));
    int b = i >> 15;
    atomicAdd(&g_ft[((b * RR + ir) * RP + it) * RP + ip], w);
}

// ---------------- conv1 (unchanged known-good) -----------------------------------
template<int ICT, int OCT, int OCB, int ROWS, int NGRP, int CPT>
__global__ void k_cgemm(const float* __restrict__ in,
                        const float* __restrict__ Wp,
                        const float* __restrict__ bias,
                        float* __restrict__ outp) {
    extern __shared__ __align__(16) float sm[];
    float* s_in = sm;                                  // [ICT][ROWS+2][40]
    float* s_w = sm + ICT * (ROWS + 2) * 40;           // [ICT*9][OCB]
    const int nthr = (OCB / 4) * NGRP;
    const int tid = threadIdx.x;
    const int rt = blockIdx.x;
    const int ocg = blockIdx.y;
    const int b = blockIdx.z;
    const int r0 = rt * ROWS;

    const int ng = tid % NGRP;
    const int ocq = tid / NGRP;
    const int n0 = ng * CPT;
    const int rr = n0 >> 5;
    const int c0 = n0 & 31;
    const int op0 = ocq * 4;

    for (int i = tid; i < ICT * (ROWS + 2) * 40; i += nthr) {
        int ic = i / ((ROWS + 2) * 40), rem = i % ((ROWS + 2) * 40);
        int r = rem / 40, cc = rem % 40;
        int X = r0 + r - 1, Y = cc - 1;
        float v = 0.f;
        if (X >= 0 && X < 32 && Y >= 0 && Y < 32)
            v = in[((b * ICT + ic) * 32 + X) * 32 + Y];
        s_in[i] = v;
    }
    {
        float4* dst = (float4*)s_w;
        const int nf4 = ICT * 9 * OCB / 4;
        for (int i = tid; i < nf4; i += nthr) {
            int k = i / (OCB / 4), o4 = i % (OCB / 4);
            dst[i] = *(const float4*)&Wp[k * OCT + ocg * OCB + o4 * 4];
        }
    }
    unsigned long long acc[2][CPT];
    {
        float b0 = bias[ocg * OCB + op0 + 0], b1 = bias[ocg * OCB + op0 + 1];
        float b2_ = bias[ocg * OCB + op0 + 2], b3 = bias[ocg * OCB + op0 + 3];
        unsigned long long p0 = pack2(b0, b1), p1 = pack2(b2_, b3);
        #pragma unroll
        for (int j = 0; j < CPT; j++) { acc[0][j] = p0; acc[1][j] = p1; }
    }
    __syncthreads();

    #pragma unroll 2
    for (int ic = 0; ic < ICT; ic++) {
        #pragma unroll
        for (int dy = 0; dy < 3; dy++) {
            const float* fp = &s_in[(ic * (ROWS + 2) + rr + dy) * 40 + c0];
            unsigned long long dup[CPT + 2];
            float2 fa = *(const float2*)fp;
            float2 fb = *(const float2*)(fp + 2);
            dup[0] = pack2(fa.x, fa.x); dup[1] = pack2(fa.y, fa.y);
            dup[2] = pack2(fb.x, fb.x); dup[3] = pack2(fb.y, fb.y);
            #pragma unroll
            for (int dx = 0; dx < 3; dx++) {
                int k = ic * 9 + dy * 3 + dx;
                ulonglong2 wv = *(const ulonglong2*)&s_w[k * OCB + op0];
                #pragma unroll
                for (int j = 0; j < CPT; j++) {
                    acc[0][j] = ffma2(wv.x, dup[j + dx], acc[0][j]);
                    acc[1][j] = ffma2(wv.y, dup[j + dx], acc[1][j]);
                }
            }
        }
    }

    float v[4][CPT];
    #pragma unroll
    for (int p = 0; p < 2; p++)
        #pragma unroll
        for (int j = 0; j < CPT; j++) {
            float lo, hi;
            unpack2(acc[p][j], lo, hi);
            v[2 * p][j] = fmaxf(lo, 0.f);
            v[2 * p + 1][j] = fmaxf(hi, 0.f);
        }
    #pragma unroll
    for (int o = 0; o < 4; o++) {
        float* dst = &outp[((b * OCT + ocg * OCB + op0 + o) * 32 + r0 + rr) * 32 + c0];
        *(float2*)dst = make_float2(v[o][0], v[o][1]);
    }
}

// ---------------- conv2 (unchanged from R12; known ~20us) ------------------------
#define SMEM_C2W ((32 * 4 * 40 + 288 * 64) * 4)
__global__ void k_conv2w(const float* __restrict__ in,
                         const float* __restrict__ Wp,
                         const float* __restrict__ bias,
                         float* __restrict__ outp) {
    extern __shared__ __align__(16) float sm[];
    float* s_in = sm;                 // [32 ic][4 rows][40]
    float* s_w = sm + 32 * 4 * 40;    // [288 k][64 oc]
    const int tid = threadIdx.x;      // 256
    const int rt = blockIdx.x;        // 16
    const int b = blockIdx.y;         // 8
    const int r0 = rt * 2;
    const int lane = tid & 31;
    const int ocq = tid >> 5;
    const int n0 = lane * 2;
    const int rr = n0 >> 5;
    const int c0 = n0 & 31;
    const int op0 = ocq * 8;

    for (int i = tid; i < 32 * 4 * 40; i += 256) {
        int ic = i / 160, rem = i % 160;
        int r = rem / 40, cc = rem % 40;
        int X = r0 + r - 1, Y = cc - 1;
        float v = 0.f;
        if (X >= 0 && X < 32 && Y >= 0 && Y < 32)
            v = in[((b * 32 + ic) * 32 + X) * 32 + Y];
        s_in[i] = v;
    }
    {
        float4* dst = (float4*)s_w;
        const float4* src = (const float4*)Wp;
        #pragma unroll
        for (int j = 0; j < 18; j++) dst[tid + j * 256] = src[tid + j * 256];
    }
    unsigned long long acc[4][2];
    #pragma unroll
    for (int p = 0; p < 4; p++) {
        unsigned long long bp = pack2(bias[op0 + 2 * p], bias[op0 + 2 * p + 1]);
        acc[p][0] = bp; acc[p][1] = bp;
    }
    __syncthreads();

    #pragma unroll 2
    for (int ic = 0; ic < 32; ic++) {
        #pragma unroll
        for (int dy = 0; dy < 3; dy++) {
            const float* fp = &s_in[(ic * 4 + rr + dy) * 40 + c0];
            float2 fa = *(const float2*)fp;
            float2 fb = *(const float2*)(fp + 2);
            unsigned long long dup[4];
            dup[0] = pack2(fa.x, fa.x); dup[1] = pack2(fa.y, fa.y);
            dup[2] = pack2(fb.x, fb.x); dup[3] = pack2(fb.y, fb.y);
            #pragma unroll
            for (int dx = 0; dx < 3; dx++) {
                const ulonglong2* wp2 =
                    (const ulonglong2*)&s_w[(ic * 9 + dy * 3 + dx) * 64 + op0];
                ulonglong2 w0 = wp2[0];
                ulonglong2 w1 = wp2[1];
                #pragma unroll
                for (int j = 0; j < 2; j++) {
                    acc[0][j] = ffma2(w0.x, dup[j + dx], acc[0][j]);
                    acc[1][j] = ffma2(w0.y, dup[j + dx], acc[1][j]);
                    acc[2][j] = ffma2(w1.x, dup[j + dx], acc[2][j]);
                    acc[3][j] = ffma2(w1.y, dup[j + dx], acc[3][j]);
                }
            }
        }
    }

    #pragma unroll
    for (int p = 0; p < 4; p++) {
        float lo0, hi0, lo1, hi1;
        unpack2(acc[p][0], lo0, hi0);
        unpack2(acc[p][1], lo1, hi1);
        int oc0 = op0 + 2 * p;
        float* d0 = &outp[((b * 64 + oc0) * 32 + r0 + rr) * 32 + c0];
        float* d1 = &outp[((b * 64 + oc0 + 1) * 32 + r0 + rr) * 32 + c0];
        *(float2*)d0 = make_float2(fmaxf(lo0, 0.f), fmaxf(lo1, 0.f));
        *(float2*)d1 = make_float2(fmaxf(hi0, 0.f), fmaxf(hi1, 0.f));
    }
}

// ---------------- ft_max[b,c] = (sum_xy h * wq[y]) * sum_g Wg[c,g] --------------
__global__ void k_ftmax(const float* __restrict__ Wg) {
    int bc = blockIdx.x;                  // 512
    int tid = threadIdx.x;                // 256
    const float* h = g_h2 + bc * 1024;
    float s = 0.f;
    for (int i = tid; i < 1024; i += 256) s += h[i] * g_wq[i & 31];
    __shared__ float red[8];
    for (int o = 16; o > 0; o >>= 1) s += __shfl_down_sync(0xffffffffu, s, o);
    if ((tid & 31) == 0) red[tid >> 5] = s;
    __syncthreads();
    if (tid == 0) {
        float tot = 0.f;
        for (int w = 0; w < 8; w++) tot += red[w];
        int c = bc & 63;
        float sw = 0.f;
        for (int g = 0; g < 32; g++) sw += Wg[c * 32 + g];
        g_ftmax[bc] = tot * sw;
    }
}

// ---------------- B[b,d] = b1[d] + sum_c W1[d, 64+c] * ftmax[b,c] ---------------
__global__ void k_bvec(const float* __restrict__ W1, const float* __restrict__ b1) {
    int i = threadIdx.x;                  // 512
    int b = i >> 6, d = i & 63;
    float s = b1[d];
    for (int c = 0; c < 64; c++) s += W1[d * 128 + 64 + c] * g_ftmax[b * 64 + c];
    g_Bvec[i] = s;
}

// ---------------- fused head: warp-per-xy, relu-sparsity-aware ------------------
// Block = 8 warps = 8 xy. Per warp: compact active c (h != 0) via ballot, GEMM1
// over active c only (exact: skipped terms are exact zeros), P stays in regs,
// relu in regs, GEMM2 with warp-vote skip on all-zero d-pairs.
// W1 in smem as plain float [c][64 d]; ulonglong2 reads give natural d-pairs.
#define SMEM_MAIN2 (16384 + 8192 + 8192 + 2048 + 256 + 128 + 2048)
__global__ void __launch_bounds__(256, 2) k_main(
    const float* __restrict__ Wg, const float* __restrict__ b2,
    float* __restrict__ out) {
    extern __shared__ __align__(16) char dsm[];
    float* s_w1t = (float*)dsm;                                  // [c][64 d] plain
    float* s_w2t = (float*)(dsm + 16384);                        // [d][32 e]
    float* s_wg  = (float*)(dsm + 16384 + 8192);                 // [c][32 g]
    float* s_h   = (float*)(dsm + 16384 + 16384);                // [c][8 xy]
    float* s_B   = (float*)(dsm + 16384 + 16384 + 2048);         // [64]
    float* s_b2  = s_B + 64;                                     // [32]
    int*   s_act = (int*)(dsm + 16384 + 16384 + 2048 + 384);     // [8][64]

    const int tid = threadIdx.x;
    const int w = tid >> 5, lane = tid & 31;
    const int b = blockIdx.y;
    const int pos0 = blockIdx.x * 8;
    const int xy = pos0 + w;

    // ---- fills (coalesced) ----
    {
        const float4* src1 = (const float4*)g_w1t;    // 1024 float4
        float4* dst1 = (float4*)s_w1t;
        #pragma unroll
        for (int i = 0; i < 4; i++) dst1[tid + i * 256] = src1[tid + i * 256];
        const float4* src2 = (const float4*)g_w2t;    // 512 float4
        float4* dst2 = (float4*)s_w2t;
        #pragma unroll
        for (int i = 0; i < 2; i++) dst2[tid + i * 256] = src2[tid + i * 256];
        float4* dst3 = (float4*)s_wg;
        #pragma unroll
        for (int i = 0; i < 2; i++) dst3[tid + i * 256] = *(const float4*)&Wg[(tid + i * 256) * 4];
    }
    #pragma unroll
    for (int i = 0; i < 2; i++) {
        int idx = tid + i * 256;                      // 512 = 64c x 8xy
        int c = idx >> 3, x = idx & 7;
        s_h[idx] = g_h2[(b * 64 + c) * 1024 + pos0 + x];
    }
    if (tid < 64) s_B[tid] = g_Bvec[b * 64 + tid];
    if (tid < 32) s_b2[tid] = b2[tid];
    __syncthreads();

    // ---- per-warp compaction of active c (h[c,xy] != 0) ----
    const unsigned full = 0xffffffffu;
    float h0 = s_h[lane * 8 + w];
    float h1 = s_h[(lane + 32) * 8 + w];
    unsigned m0 = __ballot_sync(full, h0 != 0.f);
    unsigned m1 = __ballot_sync(full, h1 != 0.f);
    int base0 = __popc(m0);
    unsigned ltmask = (1u << lane) - 1u;
    if (h0 != 0.f) s_act[w * 64 + __popc(m0 & ltmask)] = lane;
    if (h1 != 0.f) s_act[w * 64 + base0 + __popc(m1 & ltmask)] = lane + 32;
    int na = base0 + __popc(m1);
    __syncwarp();

    // ---- GEMM1: acc[j] = d-pair (2j, 2j+1), init with B, sum over active c ----
    unsigned long long acc[32];
    #pragma unroll
    for (int i = 0; i < 32; i++) acc[i] = *(const unsigned long long*)&s_B[2 * i];

    for (int k = 0; k < na; k++) {
        int c = s_act[w * 64 + k];
        float u = s_h[c * 8 + w] * s_wg[c * 32 + lane];
        unsigned long long ud = pack2(u, u);
        const ulonglong2* wr = (const ulonglong2*)(s_w1t + c * 64);
        #pragma unroll
        for (int i = 0; i < 16; i++) {
            ulonglong2 v = wr[i];                     // d-pairs (4i,4i+1),(4i+2,4i+3)
            acc[2 * i]     = ffma2(v.x, ud, acc[2 * i]);
            acc[2 * i + 1] = ffma2(v.y, ud, acc[2 * i + 1]);
        }
    }

    // ---- GEMM2: out[32 e][g=lane]; relu in regs; vote-skip all-zero d-pairs ----
    unsigned long long acc2[16];
    #pragma unroll
    for (int j = 0; j < 16; j++) acc2[j] = 0ull;
    #pragma unroll 1
    for (int i = 0; i < 32; i++) {
        float lo, hi;
        unpack2(acc[i], lo, hi);                      // lo = relu in d=2i, hi = d=2i+1
        lo = fmaxf(lo, 0.f);
        hi = fmaxf(hi, 0.f);
        if (!__all_sync(full, (lo == 0.f) && (hi == 0.f))) {
            unsigned long long d0 = pack2(lo, lo);
            unsigned long long d1 = pack2(hi, hi);
            const ulonglong2* wd0 = (const ulonglong2*)(s_w2t + (2 * i) * 32);
            const ulonglong2* wd1 = (const ulonglong2*)(s_w2t + (2 * i + 1) * 32);
            #pragma unroll
            for (int j = 0; j < 4; j++) {
                ulonglong2 v0 = wd0[j];
                acc2[2 * j]     = ffma2(v0.x, d0, acc2[2 * j]);
                acc2[2 * j + 1] = ffma2(v0.y, d0, acc2[2 * j + 1]);
            }
            #pragma unroll
            for (int j = 0; j < 4; j++) {
                ulonglong2 v1 = wd1[j];
                acc2[2 * j]     = ffma2(v1.x, d1, acc2[2 * j]);
                acc2[2 * j + 1] = ffma2(v1.y, d1, acc2[2 * j + 1]);
            }
            #pragma unroll
            for (int j = 4; j < 8; j++) {
                ulonglong2 v0 = wd0[j];
                acc2[2 * j]     = ffma2(v0.x, d0, acc2[2 * j]);
                acc2[2 * j + 1] = ffma2(v0.y, d0, acc2[2 * j + 1]);
            }
            #pragma unroll
            for (int j = 4; j < 8; j++) {
                ulonglong2 v1 = wd1[j];
                acc2[2 * j]     = ffma2(v1.x, d1, acc2[2 * j]);
                acc2[2 * j + 1] = ffma2(v1.y, d1, acc2[2 * j + 1]);
            }
        }
    }

    // ---- epilogue: +b2, store (coalesced over g=lane per e-plane) ----
    float* op = out + (((size_t)b * 32) * 1024 + xy) * 32 + lane;
    #pragma unroll
    for (int j = 0; j < 16; j++) {
        float lo, hi;
        unpack2(acc2[j], lo, hi);
        op[(size_t)(2 * j) * 32768]     = lo + s_b2[2 * j];
        op[(size_t)(2 * j + 1) * 32768] = hi + s_b2[2 * j + 1];
    }
}

// ---------------- ft_g max + g_ft re-zero for next replay -----------------------
__global__ void k_ftg(const float* __restrict__ outv, float* __restrict__ tail) {
    int bc = blockIdx.x;                   // 256
    int tid = threadIdx.x;                 // 256
    g_ft[bc * 256 + tid] = 0.f;            // cleanup: 256*256 = 65536 covers g_ft
    const float4* p = (const float4*)(outv + (size_t)bc * 32768);
    float m = -3.4e38f;
    for (int i = tid; i < 8192; i += 256) {
        float4 v = p[i];
        m = fmaxf(m, fmaxf(fmaxf(v.x, v.y), fmaxf(v.z, v.w)));
    }
    __shared__ float red[8];
    for (int o = 16; o > 0; o >>= 1) m = fmaxf(m, __shfl_xor_sync(0xffffffffu, m, o));
    if ((tid & 31) == 0) red[tid >> 5] = m;
    __syncthreads();
    if (tid == 0) {
        for (int i = 1; i < 8; i++) m = fmaxf(m, red[i]);
        tail[bc] = m;
    }
}

// ---------------- launch --------------------------------------------------------
#define SMEM_C1 ((8 * 4 * 40 + 72 * 32) * 4)

extern "C" void kernel_launch(void* const* d_in, const int* in_sizes, int n_in,
                              void* d_out, int out_size) {
    const float* pts   = (const float*)d_in[0];
    const float* scale = (const float*)d_in[1];
    const float* sigma = (const float*)d_in[2];
    const float* A     = (const float*)d_in[3];
    const float* icmp  = (const float*)d_in[4];
    int base = (n_in >= 16) ? 7 : 5;     // skip res_pt/res_r int scalars if present
    const float* Ws1 = (const float*)d_in[base + 0];
    const float* bs1 = (const float*)d_in[base + 1];
    const float* Ws2 = (const float*)d_in[base + 2];
    const float* bs2 = (const float*)d_in[base + 3];
    const float* Wg  = (const float*)d_in[base + 4];
    const float* W1  = (const float*)d_in[base + 5];
    const float* b1  = (const float*)d_in[base + 6];
    const float* W2  = (const float*)d_in[base + 7];
    const float* b2  = (const float*)d_in[base + 8];
    float* out = (float*)d_out;

    float *ftp = nullptr, *h1p = nullptr, *h2p = nullptr, *wc1p = nullptr, *wc2p = nullptr;
    cudaGetSymbolAddress((void**)&ftp, g_ft);
    cudaGetSymbolAddress((void**)&h1p, g_h1);
    cudaGetSymbolAddress((void**)&h2p, g_h2);
    cudaGetSymbolAddress((void**)&wc1p, g_wc1);
    cudaGetSymbolAddress((void**)&wc2p, g_wc2);

    static int attr_done = 0;
    if (!attr_done) {
        cudaFuncSetAttribute(k_main, cudaFuncAttributeMaxDynamicSharedMemorySize, SMEM_MAIN2);
        cudaFuncSetAttribute(k_conv2w, cudaFuncAttributeMaxDynamicSharedMemorySize, SMEM_C2W);
        attr_done = 1;
    }

    k_init<<<72, 256>>>(Ws1, Ws2, W1, W2);
    k_scatter<<<(NB * NPT + 255) / 256, 256>>>(pts, scale, sigma, A, icmp);
    // conv1: 8->32, ROWS=2, CPT=2, NGRP=32 -> 256 threads, grid (16,1,8) = 128 blocks
    k_cgemm<8, 32, 32, 2, 32, 2><<<dim3(16, 1, 8), 256, SMEM_C1>>>(ftp, wc1p, bs1, h1p);
    // conv2: all-64-oc blocks, grid (16,8) = 128 blocks x 256 threads
    k_conv2w<<<dim3(16, 8), 256, SMEM_C2W>>>(h1p, wc2p, bs2, h2p);
    k_ftmax<<<512, 256>>>(Wg);
    k_bvec<<<1, 512>>>(W1, b1);
    // head: warp-per-xy sparse GEMMs, grid (128, 8) x 256 threads
    k_main<<<dim3(128, NB), 256, SMEM_MAIN2>>>(Wg, b2, out);
    k_ftg<<<256, 256>>>(out, out + (size_t)NB * 32 * 1024 * 32);
}

// round 15
// speedup vs baseline: 1.3292x; 1.3292x over previous
#include <cuda_runtime.h>
#include <math.h>

#define RP 32
#define RR 8
#define NB 8
#define NPT 32768
#define PI_F 3.14159265358979323846f

// ---------------- scratch (device globals; no allocation allowed) ----------------
__device__ float g_ft[NB * RR * RP * RP];     // (b, r, theta, phi) -- zeroed at tail
__device__ float g_h1[NB * 32 * RP * RP];     // conv1 out
__device__ float g_h2[NB * 64 * RP * RP];     // conv2 out
__device__ float g_pre[NB * 64];              // fused ftmax partials (zeroed in k_init)
__device__ float g_swg[64];                   // sum_g Wg[c,:]
__device__ float g_Bvec[NB * 64];
__device__ float g_wq[RP];
__device__ float g_wc1[8 * 9 * 32];           // conv1 weights, [ic*9+k9][oc]
__device__ float g_wc2[32 * 9 * 64];          // conv2 weights, [ic*9+k9][oc]
__device__ float g_w1t[64 * 64];              // W1 head transposed: [c][d] (plain)
__device__ unsigned long long g_w2d[64 * 32]; // W2 head dup: [d][e] = {v,v}

// ---------------- f32x2 packed helpers ------------------------------------------
__device__ __forceinline__ unsigned long long ffma2(unsigned long long a,
                                                    unsigned long long b,
                                                    unsigned long long c) {
    unsigned long long d;
    asm("fma.rn.f32x2 %0, %1, %2, %3;" : "=l"(d) : "l"(a), "l"(b), "l"(c));
    return d;
}
__device__ __forceinline__ unsigned long long pack2(float lo, float hi) {
    unsigned long long d;
    asm("mov.b64 %0, {%1, %2};" : "=l"(d) : "f"(lo), "f"(hi));
    return d;
}
__device__ __forceinline__ void unpack2(unsigned long long v, float& lo, float& hi) {
    asm("mov.b64 {%0, %1}, %2;" : "=f"(lo), "=f"(hi) : "l"(v));
}

// ---------------- init: weights re-layouts + wq + pre-zero ----------------------
__global__ void k_init(const float* __restrict__ Wc1, const float* __restrict__ Wc2,
                       const float* __restrict__ W1h, const float* __restrict__ W2h,
                       const float* __restrict__ Wg) {
    int i = blockIdx.x * blockDim.x + threadIdx.x;   // 72 * 256 = 18432 threads
    if (i < RP) {
        double jj = (double)i;
        double theta = M_PI * (2.0 * jj + 1.0) / 64.0;
        double s = 0.0;
        for (int k = 0; k < 16; k++)
            s += sin((2.0 * jj + 1.0) * (2.0 * k + 1.0) * M_PI / 64.0) / (2.0 * k + 1.0);
        g_wq[i] = (float)((2.0 / 16.0) * sin(theta) * s);
    }
    if (i < NB * 64) g_pre[i] = 0.f;
    if (i >= 64 && i < 128) {                        // g_swg[c] = sum_g Wg[c,:]
        int c = i - 64;
        float s = 0.f;
        for (int g = 0; g < 32; g++) s += Wg[c * 32 + g];
        g_swg[c] = s;
    }
    if (i < 8 * 9 * 32) {                            // conv1 weights transpose
        int ic9 = i >> 5, oc = i & 31;
        g_wc1[i] = Wc1[oc * 72 + ic9];
    }
    if (i < 32 * 9 * 64) {                           // conv2 weights transpose
        int ic9 = i >> 6, oc = i & 63;
        g_wc2[i] = Wc2[oc * 288 + ic9];
    }
    if (i < 4096) {                                  // head W1 transpose [c][d]
        int c = i >> 6, d = i & 63;
        g_w1t[i] = W1h[d * 128 + c];
    }
    if (i < 2048) {                                  // head W2 dup [d][e]
        int d = i >> 5, e = i & 31;
        float v = W2h[e * 64 + d];
        g_w2d[i] = pack2(v, v);
    }
}

// ---------------- scatter: gaussian splat of w into (b, r, t, p) grid ------------
__global__ void __launch_bounds__(256) k_scatter(const float* __restrict__ pts,
                          const float* __restrict__ scp, const float* __restrict__ sgp,
                          const float* __restrict__ Ap, const float* __restrict__ icp) {
    int i = blockIdx.x * blockDim.x + threadIdx.x;
    if (i >= NB * NPT) return;
    float scale = *scp, sigma = *sgp, A = *Ap, icc = *icp;
    float x = pts[i * 3 + 0], y = pts[i * 3 + 1], z = pts[i * 3 + 2];
    float r = fmaxf(sqrtf(x * x + y * y + z * z), 0.1f);
    float th = acosf(fminf(fmaxf(__fdividef(z, r), -1.f), 1.f));
    float ph = atan2f(y, x) + PI_F;
    float ct = th * (float)(RP / M_PI);
    float cp = ph * (float)(RP / (2.0 * M_PI));
    float cr = __fdividef(r, scale) * (float)RR;
    int it = min(max((int)floorf(ct), 0), RP - 1);
    int ip = min(max((int)floorf(cp), 0), RP - 1);
    int ir = min(max((int)floorf(cr), 0), RR - 1);
    float dt = ct - ((float)it + icc);
    float dp = cp - ((float)ip + icc);
    float dr = cr - ((float)ir + icc);
    float d2 = dt * dt + dp * dp + dr * dr;
    float w = A * __expf(-d2 * __fdividef(0.5f, sigma * sigma));
    int b = i >> 15;
    atomicAdd(&g_ft[((b * RR + ir) * RP + it) * RP + ip], w);
}

// ---------------- conv1 (unchanged known-good) -----------------------------------
template<int ICT, int OCT, int OCB, int ROWS, int NGRP, int CPT>
__global__ void k_cgemm(const float* __restrict__ in,
                        const float* __restrict__ Wp,
                        const float* __restrict__ bias,
                        float* __restrict__ outp) {
    extern __shared__ __align__(16) float sm[];
    float* s_in = sm;                                  // [ICT][ROWS+2][40]
    float* s_w = sm + ICT * (ROWS + 2) * 40;           // [ICT*9][OCB]
    const int nthr = (OCB / 4) * NGRP;
    const int tid = threadIdx.x;
    const int rt = blockIdx.x;
    const int ocg = blockIdx.y;
    const int b = blockIdx.z;
    const int r0 = rt * ROWS;

    const int ng = tid % NGRP;
    const int ocq = tid / NGRP;
    const int n0 = ng * CPT;
    const int rr = n0 >> 5;
    const int c0 = n0 & 31;
    const int op0 = ocq * 4;

    for (int i = tid; i < ICT * (ROWS + 2) * 40; i += nthr) {
        int ic = i / ((ROWS + 2) * 40), rem = i % ((ROWS + 2) * 40);
        int r = rem / 40, cc = rem % 40;
        int X = r0 + r - 1, Y = cc - 1;
        float v = 0.f;
        if (X >= 0 && X < 32 && Y >= 0 && Y < 32)
            v = in[((b * ICT + ic) * 32 + X) * 32 + Y];
        s_in[i] = v;
    }
    {
        float4* dst = (float4*)s_w;
        const int nf4 = ICT * 9 * OCB / 4;
        for (int i = tid; i < nf4; i += nthr) {
            int k = i / (OCB / 4), o4 = i % (OCB / 4);
            dst[i] = *(const float4*)&Wp[k * OCT + ocg * OCB + o4 * 4];
        }
    }
    unsigned long long acc[2][CPT];
    {
        float b0 = bias[ocg * OCB + op0 + 0], b1 = bias[ocg * OCB + op0 + 1];
        float b2_ = bias[ocg * OCB + op0 + 2], b3 = bias[ocg * OCB + op0 + 3];
        unsigned long long p0 = pack2(b0, b1), p1 = pack2(b2_, b3);
        #pragma unroll
        for (int j = 0; j < CPT; j++) { acc[0][j] = p0; acc[1][j] = p1; }
    }
    __syncthreads();

    #pragma unroll 2
    for (int ic = 0; ic < ICT; ic++) {
        #pragma unroll
        for (int dy = 0; dy < 3; dy++) {
            const float* fp = &s_in[(ic * (ROWS + 2) + rr + dy) * 40 + c0];
            unsigned long long dup[CPT + 2];
            float2 fa = *(const float2*)fp;
            float2 fb = *(const float2*)(fp + 2);
            dup[0] = pack2(fa.x, fa.x); dup[1] = pack2(fa.y, fa.y);
            dup[2] = pack2(fb.x, fb.x); dup[3] = pack2(fb.y, fb.y);
            #pragma unroll
            for (int dx = 0; dx < 3; dx++) {
                int k = ic * 9 + dy * 3 + dx;
                ulonglong2 wv = *(const ulonglong2*)&s_w[k * OCB + op0];
                #pragma unroll
                for (int j = 0; j < CPT; j++) {
                    acc[0][j] = ffma2(wv.x, dup[j + dx], acc[0][j]);
                    acc[1][j] = ffma2(wv.y, dup[j + dx], acc[1][j]);
                }
            }
        }
    }

    float v[4][CPT];
    #pragma unroll
    for (int p = 0; p < 2; p++)
        #pragma unroll
        for (int j = 0; j < CPT; j++) {
            float lo, hi;
            unpack2(acc[p][j], lo, hi);
            v[2 * p][j] = fmaxf(lo, 0.f);
            v[2 * p + 1][j] = fmaxf(hi, 0.f);
        }
    #pragma unroll
    for (int o = 0; o < 4; o++) {
        float* dst = &outp[((b * OCT + ocg * OCB + op0 + o) * 32 + r0 + rr) * 32 + c0];
        *(float2*)dst = make_float2(v[o][0], v[o][1]);
    }
}

// ---------------- conv2 + fused ftmax partial ------------------------------------
#define SMEM_C2W ((32 * 4 * 40 + 288 * 64) * 4)
__global__ void k_conv2w(const float* __restrict__ in,
                         const float* __restrict__ Wp,
                         const float* __restrict__ bias,
                         float* __restrict__ outp) {
    extern __shared__ __align__(16) float sm[];
    float* s_in = sm;                 // [32 ic][4 rows][40]
    float* s_w = sm + 32 * 4 * 40;    // [288 k][64 oc]
    const int tid = threadIdx.x;      // 256
    const int rt = blockIdx.x;        // 16
    const int b = blockIdx.y;         // 8
    const int r0 = rt * 2;
    const int lane = tid & 31;
    const int ocq = tid >> 5;
    const int n0 = lane * 2;
    const int rr = n0 >> 5;
    const int c0 = n0 & 31;
    const int op0 = ocq * 8;

    for (int i = tid; i < 32 * 4 * 40; i += 256) {
        int ic = i / 160, rem = i % 160;
        int r = rem / 40, cc = rem % 40;
        int X = r0 + r - 1, Y = cc - 1;
        float v = 0.f;
        if (X >= 0 && X < 32 && Y >= 0 && Y < 32)
            v = in[((b * 32 + ic) * 32 + X) * 32 + Y];
        s_in[i] = v;
    }
    {
        float4* dst = (float4*)s_w;
        const float4* src = (const float4*)Wp;
        #pragma unroll
        for (int j = 0; j < 18; j++) dst[tid + j * 256] = src[tid + j * 256];
    }
    unsigned long long acc[4][2];
    #pragma unroll
    for (int p = 0; p < 4; p++) {
        unsigned long long bp = pack2(bias[op0 + 2 * p], bias[op0 + 2 * p + 1]);
        acc[p][0] = bp; acc[p][1] = bp;
    }
    const float wq0 = g_wq[c0];
    const float wq1 = g_wq[c0 + 1];
    __syncthreads();

    #pragma unroll 2
    for (int ic = 0; ic < 32; ic++) {
        #pragma unroll
        for (int dy = 0; dy < 3; dy++) {
            const float* fp = &s_in[(ic * 4 + rr + dy) * 40 + c0];
            float2 fa = *(const float2*)fp;
            float2 fb = *(const float2*)(fp + 2);
            unsigned long long dup[4];
            dup[0] = pack2(fa.x, fa.x); dup[1] = pack2(fa.y, fa.y);
            dup[2] = pack2(fb.x, fb.x); dup[3] = pack2(fb.y, fb.y);
            #pragma unroll
            for (int dx = 0; dx < 3; dx++) {
                const ulonglong2* wp2 =
                    (const ulonglong2*)&s_w[(ic * 9 + dy * 3 + dx) * 64 + op0];
                ulonglong2 w0 = wp2[0];
                ulonglong2 w1 = wp2[1];
                #pragma unroll
                for (int j = 0; j < 2; j++) {
                    acc[0][j] = ffma2(w0.x, dup[j + dx], acc[0][j]);
                    acc[1][j] = ffma2(w0.y, dup[j + dx], acc[1][j]);
                    acc[2][j] = ffma2(w1.x, dup[j + dx], acc[2][j]);
                    acc[3][j] = ffma2(w1.y, dup[j + dx], acc[3][j]);
                }
            }
        }
    }

    // ---- epilogue: relu + store + fused ftmax partial (h * wq[col]) ----
    #pragma unroll
    for (int p = 0; p < 4; p++) {
        float lo0, hi0, lo1, hi1;
        unpack2(acc[p][0], lo0, hi0);
        unpack2(acc[p][1], lo1, hi1);
        lo0 = fmaxf(lo0, 0.f); hi0 = fmaxf(hi0, 0.f);
        lo1 = fmaxf(lo1, 0.f); hi1 = fmaxf(hi1, 0.f);
        int oc0 = op0 + 2 * p;
        float* d0 = &outp[((b * 64 + oc0) * 32 + r0 + rr) * 32 + c0];
        float* d1 = &outp[((b * 64 + oc0 + 1) * 32 + r0 + rr) * 32 + c0];
        *(float2*)d0 = make_float2(lo0, lo1);
        *(float2*)d1 = make_float2(hi0, hi1);
        // partial sums over this thread's 2 columns, weighted by wq[col]
        float pa = lo0 * wq0 + lo1 * wq1;      // oc0
        float pb = hi0 * wq0 + hi1 * wq1;      // oc0+1
        #pragma unroll
        for (int o = 16; o > 0; o >>= 1) {
            pa += __shfl_xor_sync(0xffffffffu, pa, o);
            pb += __shfl_xor_sync(0xffffffffu, pb, o);
        }
        if (lane == 0) {
            atomicAdd(&g_pre[b * 64 + oc0], pa);
            atomicAdd(&g_pre[b * 64 + oc0 + 1], pb);
        }
    }
}

// ---------------- head prep: ftmax = pre * swg; B = b1 + W1b @ ftmax -------------
__global__ void k_head(const float* __restrict__ W1, const float* __restrict__ b1) {
    __shared__ float sftm[NB * 64];
    int i = threadIdx.x;                  // 512
    int b = i >> 6, d = i & 63;
    sftm[i] = g_pre[i] * g_swg[i & 63];
    __syncthreads();
    float s = b1[d];
    for (int c = 0; c < 64; c++) s += W1[d * 128 + 64 + c] * sftm[b * 64 + c];
    g_Bvec[i] = s;
}

// ---------------- fused head: register-tiled GEMM over n = (xy, g) --------------
// (EXACT R12/R8 version — known-good)
#define SMEM_MAIN (65536 + 16384 + 16384 + 256 + 128)
__global__ void __launch_bounds__(256, 2) k_main(
    const float* __restrict__ Wg, const float* __restrict__ b2,
    float* __restrict__ out) {
    extern __shared__ __align__(16) char dsm[];
    float* s_u = (float*)dsm;                                   // 64c x 256n (also D1 as [d][n])
    float* s_w1t = (float*)(dsm + 65536);                       // [c][64 d]
    unsigned long long* s_w2d = (unsigned long long*)(dsm + 65536 + 16384);  // [d][32 e] dup
    float* s_B = (float*)(dsm + 65536 + 32768);
    float* s_b2 = s_B + 64;

    const int tid = threadIdx.x;
    const int b = blockIdx.y;
    const int pos0 = blockIdx.x * 8;     // 8 xy per block

    {
        const float4* src1 = (const float4*)g_w1t;
        float4* dst1 = (float4*)s_w1t;
        #pragma unroll
        for (int i = 0; i < 4; i++) dst1[tid + i * 256] = src1[tid + i * 256];
        const float4* src2 = (const float4*)g_w2d;
        float4* dst2 = (float4*)s_w2d;
        #pragma unroll
        for (int i = 0; i < 4; i++) dst2[tid + i * 256] = src2[tid + i * 256];
    }
    if (tid < 64) s_B[tid] = g_Bvec[b * 64 + tid];
    if (tid < 32) s_b2[tid] = b2[tid];
    #pragma unroll 4
    for (int i = tid; i < 16384; i += 256) {
        int c = i >> 8, nl = i & 255;
        s_u[i] = g_h2[(b * 64 + c) * 1024 + pos0 + (nl >> 5)] * Wg[c * 32 + (nl & 31)];
    }
    __syncthreads();

    const int n0 = (tid & 63) * 4;
    const int d0 = (tid >> 6) * 16;
    unsigned long long acc[8][4];
    #pragma unroll
    for (int i = 0; i < 8; i++)
        #pragma unroll
        for (int j = 0; j < 4; j++) acc[i][j] = 0ull;

    {
        const float* up = s_u + n0;
        const float* wp = s_w1t + d0;
        #pragma unroll 2
        for (int c = 0; c < 64; c++) {
            float4 u4 = *(const float4*)(up + c * 256);
            unsigned long long ud0 = pack2(u4.x, u4.x);
            unsigned long long ud1 = pack2(u4.y, u4.y);
            unsigned long long ud2 = pack2(u4.z, u4.z);
            unsigned long long ud3 = pack2(u4.w, u4.w);
            const ulonglong2* wr = (const ulonglong2*)(wp + c * 64);
            #pragma unroll
            for (int i = 0; i < 4; i++) {
                ulonglong2 wv = wr[i];
                acc[2 * i][0] = ffma2(wv.x, ud0, acc[2 * i][0]);
                acc[2 * i][1] = ffma2(wv.x, ud1, acc[2 * i][1]);
                acc[2 * i][2] = ffma2(wv.x, ud2, acc[2 * i][2]);
                acc[2 * i][3] = ffma2(wv.x, ud3, acc[2 * i][3]);
                acc[2 * i + 1][0] = ffma2(wv.y, ud0, acc[2 * i + 1][0]);
                acc[2 * i + 1][1] = ffma2(wv.y, ud1, acc[2 * i + 1][1]);
                acc[2 * i + 1][2] = ffma2(wv.y, ud2, acc[2 * i + 1][2]);
                acc[2 * i + 1][3] = ffma2(wv.y, ud3, acc[2 * i + 1][3]);
            }
        }
    }
    __syncthreads();

    #pragma unroll
    for (int i = 0; i < 8; i++) {
        int d = d0 + 2 * i;
        float blo = s_B[d], bhi = s_B[d + 1];
        #pragma unroll
        for (int j = 0; j < 4; j++) {
            float lo, hi;
            unpack2(acc[i][j], lo, hi);
            s_u[d * 256 + n0 + j] = fmaxf(lo + blo, 0.f);
            s_u[(d + 1) * 256 + n0 + j] = fmaxf(hi + bhi, 0.f);
        }
    }
    __syncthreads();

    const int e0 = (tid >> 6) * 8;
    unsigned long long acc2[8][2];
    #pragma unroll
    for (int i = 0; i < 8; i++) { acc2[i][0] = 0ull; acc2[i][1] = 0ull; }
    {
        const float* dp = s_u + n0;
        const unsigned long long* wp2 = s_w2d + e0;
        #pragma unroll 2
        for (int d = 0; d < 64; d++) {
            ulonglong2 uu = *(const ulonglong2*)(dp + d * 256);
            const ulonglong2* wd = (const ulonglong2*)(wp2 + d * 32);
            #pragma unroll
            for (int i = 0; i < 4; i++) {
                ulonglong2 wv = wd[i];
                acc2[2 * i][0] = ffma2(wv.x, uu.x, acc2[2 * i][0]);
                acc2[2 * i][1] = ffma2(wv.x, uu.y, acc2[2 * i][1]);
                acc2[2 * i + 1][0] = ffma2(wv.y, uu.x, acc2[2 * i + 1][0]);
                acc2[2 * i + 1][1] = ffma2(wv.y, uu.y, acc2[2 * i + 1][1]);
            }
        }
    }

    const int xy = pos0 + (n0 >> 5);
    const int g0 = n0 & 31;
    #pragma unroll
    for (int e = 0; e < 8; e++) {
        float v0, v1, v2, v3;
        unpack2(acc2[e][0], v0, v1);
        unpack2(acc2[e][1], v2, v3);
        float bb = s_b2[e0 + e];
        float4 vv = make_float4(v0 + bb, v1 + bb, v2 + bb, v3 + bb);
        *(float4*)&out[(((size_t)b * 32 + e0 + e) * 1024 + xy) * 32 + g0] = vv;
    }
}

// ---------------- ft_g max + g_ft re-zero for next replay -----------------------
__global__ void k_ftg(const float* __restrict__ outv, float* __restrict__ tail) {
    int bc = blockIdx.x;                   // 256
    int tid = threadIdx.x;                 // 256
    g_ft[bc * 256 + tid] = 0.f;            // cleanup: 256*256 = 65536 covers g_ft
    const float4* p = (const float4*)(outv + (size_t)bc * 32768);
    float m = -3.4e38f;
    for (int i = tid; i < 8192; i += 256) {
        float4 v = p[i];
        m = fmaxf(m, fmaxf(fmaxf(v.x, v.y), fmaxf(v.z, v.w)));
    }
    __shared__ float red[8];
    for (int o = 16; o > 0; o >>= 1) m = fmaxf(m, __shfl_xor_sync(0xffffffffu, m, o));
    if ((tid & 31) == 0) red[tid >> 5] = m;
    __syncthreads();
    if (tid == 0) {
        for (int i = 1; i < 8; i++) m = fmaxf(m, red[i]);
        tail[bc] = m;
    }
}

// ---------------- launch --------------------------------------------------------
#define SMEM_C1 ((8 * 4 * 40 + 72 * 32) * 4)

extern "C" void kernel_launch(void* const* d_in, const int* in_sizes, int n_in,
                              void* d_out, int out_size) {
    const float* pts   = (const float*)d_in[0];
    const float* scale = (const float*)d_in[1];
    const float* sigma = (const float*)d_in[2];
    const float* A     = (const float*)d_in[3];
    const float* icmp  = (const float*)d_in[4];
    int base = (n_in >= 16) ? 7 : 5;     // skip res_pt/res_r int scalars if present
    const float* Ws1 = (const float*)d_in[base + 0];
    const float* bs1 = (const float*)d_in[base + 1];
    const float* Ws2 = (const float*)d_in[base + 2];
    const float* bs2 = (const float*)d_in[base + 3];
    const float* Wg  = (const float*)d_in[base + 4];
    const float* W1  = (const float*)d_in[base + 5];
    const float* b1  = (const float*)d_in[base + 6];
    const float* W2  = (const float*)d_in[base + 7];
    const float* b2  = (const float*)d_in[base + 8];
    float* out = (float*)d_out;

    float *ftp = nullptr, *h1p = nullptr, *h2p = nullptr, *wc1p = nullptr, *wc2p = nullptr;
    cudaGetSymbolAddress((void**)&ftp, g_ft);
    cudaGetSymbolAddress((void**)&h1p, g_h1);
    cudaGetSymbolAddress((void**)&h2p, g_h2);
    cudaGetSymbolAddress((void**)&wc1p, g_wc1);
    cudaGetSymbolAddress((void**)&wc2p, g_wc2);

    static int attr_done = 0;
    if (!attr_done) {
        cudaFuncSetAttribute(k_main, cudaFuncAttributeMaxDynamicSharedMemorySize, SMEM_MAIN);
        cudaFuncSetAttribute(k_conv2w, cudaFuncAttributeMaxDynamicSharedMemorySize, SMEM_C2W);
        attr_done = 1;
    }

    k_init<<<72, 256>>>(Ws1, Ws2, W1, W2, Wg);
    k_scatter<<<(NB * NPT + 255) / 256, 256>>>(pts, scale, sigma, A, icmp);
    // conv1: 8->32, ROWS=2, CPT=2, NGRP=32 -> 256 threads, grid (16,1,8) = 128 blocks
    k_cgemm<8, 32, 32, 2, 32, 2><<<dim3(16, 1, 8), 256, SMEM_C1>>>(ftp, wc1p, bs1, h1p);
    // conv2 (+fused ftmax partials): grid (16,8) = 128 blocks x 256 threads
    k_conv2w<<<dim3(16, 8), 256, SMEM_C2W>>>(h1p, wc2p, bs2, h2p);
    // head prep: ftmax finish + Bvec, one tiny block
    k_head<<<1, 512>>>(W1, b1);
    // head GEMMs: grid (128, 8) x 256 threads
    k_main<<<dim3(128, NB), 256, SMEM_MAIN>>>(Wg, b2, out);
    k_ftg<<<256, 256>>>(out, out + (size_t)NB * 32 * 1024 * 32);
}

// round 16
// speedup vs baseline: 1.4832x; 1.1158x over previous
#include <cuda_runtime.h>
#include <math.h>

#define RP 32
#define RR 8
#define NB 8
#define NPT 32768
#define PI_F 3.14159265358979323846f

// ---------------- scratch (device globals; no allocation allowed) ----------------
__device__ float g_ft[NB * RR * RP * RP];     // (b, r, theta, phi) -- zeroed in k_init
__device__ float g_h1[NB * 32 * RP * RP];     // conv1 out
__device__ float g_h2[NB * 64 * RP * RP];     // conv2 out
__device__ float g_pre[NB * 64];              // fused ftmax partials (zeroed in k_init)
__device__ float g_swg[64];                   // sum_g Wg[c,:]
__device__ float g_Bvec[NB * 64];
__device__ float g_wq[RP];
__device__ float g_wc1[8 * 9 * 32];           // conv1 weights, [ic*9+k9][oc]
__device__ float g_wc2[32 * 9 * 64];          // conv2 weights, [ic*9+k9][oc]
__device__ float g_w1t[64 * 64];              // W1 head transposed: [c][d] (plain)
__device__ unsigned long long g_w2d[64 * 32]; // W2 head dup: [d][e] = {v,v}
__device__ unsigned g_ftg[NB * 32];           // ft_g ordered-uint keys (zeroed in k_init)

// ---------------- f32x2 packed helpers ------------------------------------------
__device__ __forceinline__ unsigned long long ffma2(unsigned long long a,
                                                    unsigned long long b,
                                                    unsigned long long c) {
    unsigned long long d;
    asm("fma.rn.f32x2 %0, %1, %2, %3;" : "=l"(d) : "l"(a), "l"(b), "l"(c));
    return d;
}
__device__ __forceinline__ unsigned long long pack2(float lo, float hi) {
    unsigned long long d;
    asm("mov.b64 %0, {%1, %2};" : "=l"(d) : "f"(lo), "f"(hi));
    return d;
}
__device__ __forceinline__ void unpack2(unsigned long long v, float& lo, float& hi) {
    asm("mov.b64 {%0, %1}, %2;" : "=f"(lo), "=f"(hi) : "l"(v));
}
__device__ __forceinline__ unsigned fkey(float f) {
    unsigned u = __float_as_uint(f);
    return (u & 0x80000000u) ? ~u : (u | 0x80000000u);
}

// ---------------- init: weights re-layouts + wq + zero scratch -------------------
__global__ void k_init(const float* __restrict__ Wc1, const float* __restrict__ Wc2,
                       const float* __restrict__ W1h, const float* __restrict__ W2h,
                       const float* __restrict__ Wg) {
    int i = blockIdx.x * blockDim.x + threadIdx.x;   // 72 * 256 = 18432 threads
    // zero g_ft (65536) grid-stride
    for (int k = i; k < NB * RR * RP * RP; k += 18432) g_ft[k] = 0.f;
    if (i < NB * 64) g_pre[i] = 0.f;
    if (i < NB * 32) g_ftg[i] = 0u;
    if (i < RP) {
        double jj = (double)i;
        double theta = M_PI * (2.0 * jj + 1.0) / 64.0;
        double s = 0.0;
        for (int k = 0; k < 16; k++)
            s += sin((2.0 * jj + 1.0) * (2.0 * k + 1.0) * M_PI / 64.0) / (2.0 * k + 1.0);
        g_wq[i] = (float)((2.0 / 16.0) * sin(theta) * s);
    }
    if (i >= 512 && i < 576) {                       // g_swg[c] = sum_g Wg[c,:]
        int c = i - 512;
        float s = 0.f;
        for (int g = 0; g < 32; g++) s += Wg[c * 32 + g];
        g_swg[c] = s;
    }
    if (i < 8 * 9 * 32) {                            // conv1 weights transpose
        int ic9 = i >> 5, oc = i & 31;
        g_wc1[i] = Wc1[oc * 72 + ic9];
    }
    if (i < 32 * 9 * 64) {                           // conv2 weights transpose
        int ic9 = i >> 6, oc = i & 63;
        g_wc2[i] = Wc2[oc * 288 + ic9];
    }
    if (i < 4096) {                                  // head W1 transpose [c][d]
        int c = i >> 6, d = i & 63;
        g_w1t[i] = W1h[d * 128 + c];
    }
    if (i < 2048) {                                  // head W2 dup [d][e]
        int d = i >> 5, e = i & 31;
        float v = W2h[e * 64 + d];
        g_w2d[i] = pack2(v, v);
    }
}

// ---------------- scatter: gaussian splat of w into (b, r, t, p) grid ------------
__global__ void __launch_bounds__(256) k_scatter(const float* __restrict__ pts,
                          const float* __restrict__ scp, const float* __restrict__ sgp,
                          const float* __restrict__ Ap, const float* __restrict__ icp) {
    int i = blockIdx.x * blockDim.x + threadIdx.x;
    if (i >= NB * NPT) return;
    float scale = *scp, sigma = *sgp, A = *Ap, icc = *icp;
    float x = pts[i * 3 + 0], y = pts[i * 3 + 1], z = pts[i * 3 + 2];
    float r = fmaxf(sqrtf(x * x + y * y + z * z), 0.1f);
    float th = acosf(fminf(fmaxf(__fdividef(z, r), -1.f), 1.f));
    float ph = atan2f(y, x) + PI_F;
    float ct = th * (float)(RP / M_PI);
    float cp = ph * (float)(RP / (2.0 * M_PI));
    float cr = __fdividef(r, scale) * (float)RR;
    int it = min(max((int)floorf(ct), 0), RP - 1);
    int ip = min(max((int)floorf(cp), 0), RP - 1);
    int ir = min(max((int)floorf(cr), 0), RR - 1);
    float dt = ct - ((float)it + icc);
    float dp = cp - ((float)ip + icc);
    float dr = cr - ((float)ir + icc);
    float d2 = dt * dt + dp * dp + dr * dr;
    float w = A * __expf(-d2 * __fdividef(0.5f, sigma * sigma));
    int b = i >> 15;
    atomicAdd(&g_ft[((b * RR + ir) * RP + it) * RP + ip], w);
}

// ---------------- conv1 (unchanged known-good) -----------------------------------
template<int ICT, int OCT, int OCB, int ROWS, int NGRP, int CPT>
__global__ void k_cgemm(const float* __restrict__ in,
                        const float* __restrict__ Wp,
                        const float* __restrict__ bias,
                        float* __restrict__ outp) {
    extern __shared__ __align__(16) float sm[];
    float* s_in = sm;                                  // [ICT][ROWS+2][40]
    float* s_w = sm + ICT * (ROWS + 2) * 40;           // [ICT*9][OCB]
    const int nthr = (OCB / 4) * NGRP;
    const int tid = threadIdx.x;
    const int rt = blockIdx.x;
    const int ocg = blockIdx.y;
    const int b = blockIdx.z;
    const int r0 = rt * ROWS;

    const int ng = tid % NGRP;
    const int ocq = tid / NGRP;
    const int n0 = ng * CPT;
    const int rr = n0 >> 5;
    const int c0 = n0 & 31;
    const int op0 = ocq * 4;

    for (int i = tid; i < ICT * (ROWS + 2) * 40; i += nthr) {
        int ic = i / ((ROWS + 2) * 40), rem = i % ((ROWS + 2) * 40);
        int r = rem / 40, cc = rem % 40;
        int X = r0 + r - 1, Y = cc - 1;
        float v = 0.f;
        if (X >= 0 && X < 32 && Y >= 0 && Y < 32)
            v = in[((b * ICT + ic) * 32 + X) * 32 + Y];
        s_in[i] = v;
    }
    {
        float4* dst = (float4*)s_w;
        const int nf4 = ICT * 9 * OCB / 4;
        for (int i = tid; i < nf4; i += nthr) {
            int k = i / (OCB / 4), o4 = i % (OCB / 4);
            dst[i] = *(const float4*)&Wp[k * OCT + ocg * OCB + o4 * 4];
        }
    }
    unsigned long long acc[2][CPT];
    {
        float b0 = bias[ocg * OCB + op0 + 0], b1 = bias[ocg * OCB + op0 + 1];
        float b2_ = bias[ocg * OCB + op0 + 2], b3 = bias[ocg * OCB + op0 + 3];
        unsigned long long p0 = pack2(b0, b1), p1 = pack2(b2_, b3);
        #pragma unroll
        for (int j = 0; j < CPT; j++) { acc[0][j] = p0; acc[1][j] = p1; }
    }
    __syncthreads();

    #pragma unroll 2
    for (int ic = 0; ic < ICT; ic++) {
        #pragma unroll
        for (int dy = 0; dy < 3; dy++) {
            const float* fp = &s_in[(ic * (ROWS + 2) + rr + dy) * 40 + c0];
            unsigned long long dup[CPT + 2];
            float2 fa = *(const float2*)fp;
            float2 fb = *(const float2*)(fp + 2);
            dup[0] = pack2(fa.x, fa.x); dup[1] = pack2(fa.y, fa.y);
            dup[2] = pack2(fb.x, fb.x); dup[3] = pack2(fb.y, fb.y);
            #pragma unroll
            for (int dx = 0; dx < 3; dx++) {
                int k = ic * 9 + dy * 3 + dx;
                ulonglong2 wv = *(const ulonglong2*)&s_w[k * OCB + op0];
                #pragma unroll
                for (int j = 0; j < CPT; j++) {
                    acc[0][j] = ffma2(wv.x, dup[j + dx], acc[0][j]);
                    acc[1][j] = ffma2(wv.y, dup[j + dx], acc[1][j]);
                }
            }
        }
    }

    float v[4][CPT];
    #pragma unroll
    for (int p = 0; p < 2; p++)
        #pragma unroll
        for (int j = 0; j < CPT; j++) {
            float lo, hi;
            unpack2(acc[p][j], lo, hi);
            v[2 * p][j] = fmaxf(lo, 0.f);
            v[2 * p + 1][j] = fmaxf(hi, 0.f);
        }
    #pragma unroll
    for (int o = 0; o < 4; o++) {
        float* dst = &outp[((b * OCT + ocg * OCB + op0 + o) * 32 + r0 + rr) * 32 + c0];
        *(float2*)dst = make_float2(v[o][0], v[o][1]);
    }
}

// ---------------- conv2 + fused ftmax partial (unchanged from R15) ---------------
#define SMEM_C2W ((32 * 4 * 40 + 288 * 64) * 4)
__global__ void k_conv2w(const float* __restrict__ in,
                         const float* __restrict__ Wp,
                         const float* __restrict__ bias,
                         float* __restrict__ outp) {
    extern __shared__ __align__(16) float sm[];
    float* s_in = sm;                 // [32 ic][4 rows][40]
    float* s_w = sm + 32 * 4 * 40;    // [288 k][64 oc]
    const int tid = threadIdx.x;      // 256
    const int rt = blockIdx.x;        // 16
    const int b = blockIdx.y;         // 8
    const int r0 = rt * 2;
    const int lane = tid & 31;
    const int ocq = tid >> 5;
    const int n0 = lane * 2;
    const int rr = n0 >> 5;
    const int c0 = n0 & 31;
    const int op0 = ocq * 8;

    for (int i = tid; i < 32 * 4 * 40; i += 256) {
        int ic = i / 160, rem = i % 160;
        int r = rem / 40, cc = rem % 40;
        int X = r0 + r - 1, Y = cc - 1;
        float v = 0.f;
        if (X >= 0 && X < 32 && Y >= 0 && Y < 32)
            v = in[((b * 32 + ic) * 32 + X) * 32 + Y];
        s_in[i] = v;
    }
    {
        float4* dst = (float4*)s_w;
        const float4* src = (const float4*)Wp;
        #pragma unroll
        for (int j = 0; j < 18; j++) dst[tid + j * 256] = src[tid + j * 256];
    }
    unsigned long long acc[4][2];
    #pragma unroll
    for (int p = 0; p < 4; p++) {
        unsigned long long bp = pack2(bias[op0 + 2 * p], bias[op0 + 2 * p + 1]);
        acc[p][0] = bp; acc[p][1] = bp;
    }
    const float wq0 = g_wq[c0];
    const float wq1 = g_wq[c0 + 1];
    __syncthreads();

    #pragma unroll 2
    for (int ic = 0; ic < 32; ic++) {
        #pragma unroll
        for (int dy = 0; dy < 3; dy++) {
            const float* fp = &s_in[(ic * 4 + rr + dy) * 40 + c0];
            float2 fa = *(const float2*)fp;
            float2 fb = *(const float2*)(fp + 2);
            unsigned long long dup[4];
            dup[0] = pack2(fa.x, fa.x); dup[1] = pack2(fa.y, fa.y);
            dup[2] = pack2(fb.x, fb.x); dup[3] = pack2(fb.y, fb.y);
            #pragma unroll
            for (int dx = 0; dx < 3; dx++) {
                const ulonglong2* wp2 =
                    (const ulonglong2*)&s_w[(ic * 9 + dy * 3 + dx) * 64 + op0];
                ulonglong2 w0 = wp2[0];
                ulonglong2 w1 = wp2[1];
                #pragma unroll
                for (int j = 0; j < 2; j++) {
                    acc[0][j] = ffma2(w0.x, dup[j + dx], acc[0][j]);
                    acc[1][j] = ffma2(w0.y, dup[j + dx], acc[1][j]);
                    acc[2][j] = ffma2(w1.x, dup[j + dx], acc[2][j]);
                    acc[3][j] = ffma2(w1.y, dup[j + dx], acc[3][j]);
                }
            }
        }
    }

    #pragma unroll
    for (int p = 0; p < 4; p++) {
        float lo0, hi0, lo1, hi1;
        unpack2(acc[p][0], lo0, hi0);
        unpack2(acc[p][1], lo1, hi1);
        lo0 = fmaxf(lo0, 0.f); hi0 = fmaxf(hi0, 0.f);
        lo1 = fmaxf(lo1, 0.f); hi1 = fmaxf(hi1, 0.f);
        int oc0 = op0 + 2 * p;
        float* d0 = &outp[((b * 64 + oc0) * 32 + r0 + rr) * 32 + c0];
        float* d1 = &outp[((b * 64 + oc0 + 1) * 32 + r0 + rr) * 32 + c0];
        *(float2*)d0 = make_float2(lo0, lo1);
        *(float2*)d1 = make_float2(hi0, hi1);
        float pa = lo0 * wq0 + lo1 * wq1;
        float pb = hi0 * wq0 + hi1 * wq1;
        #pragma unroll
        for (int o = 16; o > 0; o >>= 1) {
            pa += __shfl_xor_sync(0xffffffffu, pa, o);
            pb += __shfl_xor_sync(0xffffffffu, pb, o);
        }
        if (lane == 0) {
            atomicAdd(&g_pre[b * 64 + oc0], pa);
            atomicAdd(&g_pre[b * 64 + oc0 + 1], pb);
        }
    }
}

// ---------------- head prep: ftmax = pre * swg; B = b1 + W1b @ ftmax -------------
// 8 blocks (one per b) x 64 threads (one per d).
__global__ void k_head(const float* __restrict__ W1, const float* __restrict__ b1) {
    __shared__ float sftm[64];
    int b = blockIdx.x;
    int d = threadIdx.x;
    sftm[d] = g_pre[b * 64 + d] * g_swg[d];
    __syncthreads();
    float s = b1[d];
    #pragma unroll 8
    for (int c = 0; c < 64; c++) s += W1[d * 128 + 64 + c] * sftm[c];
    g_Bvec[b * 64 + d] = s;
}

// ---------------- fused head GEMMs + ft_g max (smem-staged) ---------------------
#define SMEM_MAIN (65536 + 16384 + 16384 + 256 + 128)
__global__ void __launch_bounds__(256, 2) k_main(
    const float* __restrict__ Wg, const float* __restrict__ b2,
    float* __restrict__ out) {
    extern __shared__ __align__(16) char dsm[];
    float* s_u = (float*)dsm;                                   // 64c x 256n (also D1 as [d][n])
    float* s_w1t = (float*)(dsm + 65536);                       // [c][64 d]
    unsigned long long* s_w2d = (unsigned long long*)(dsm + 65536 + 16384);  // [d][32 e] dup
    float* s_B = (float*)(dsm + 65536 + 32768);
    float* s_b2 = s_B + 64;

    const int tid = threadIdx.x;
    const int b = blockIdx.y;
    const int pos0 = blockIdx.x * 8;     // 8 xy per block

    {
        const float4* src1 = (const float4*)g_w1t;
        float4* dst1 = (float4*)s_w1t;
        #pragma unroll
        for (int i = 0; i < 4; i++) dst1[tid + i * 256] = src1[tid + i * 256];
        const float4* src2 = (const float4*)g_w2d;
        float4* dst2 = (float4*)s_w2d;
        #pragma unroll
        for (int i = 0; i < 4; i++) dst2[tid + i * 256] = src2[tid + i * 256];
    }
    if (tid < 64) s_B[tid] = g_Bvec[b * 64 + tid];
    if (tid < 32) s_b2[tid] = b2[tid];
    #pragma unroll 4
    for (int i = tid; i < 16384; i += 256) {
        int c = i >> 8, nl = i & 255;
        s_u[i] = g_h2[(b * 64 + c) * 1024 + pos0 + (nl >> 5)] * Wg[c * 32 + (nl & 31)];
    }
    __syncthreads();

    const int n0 = (tid & 63) * 4;
    const int d0 = (tid >> 6) * 16;
    unsigned long long acc[8][4];
    #pragma unroll
    for (int i = 0; i < 8; i++)
        #pragma unroll
        for (int j = 0; j < 4; j++) acc[i][j] = 0ull;

    {
        const float* up = s_u + n0;
        const float* wp = s_w1t + d0;
        #pragma unroll 2
        for (int c = 0; c < 64; c++) {
            float4 u4 = *(const float4*)(up + c * 256);
            unsigned long long ud0 = pack2(u4.x, u4.x);
            unsigned long long ud1 = pack2(u4.y, u4.y);
            unsigned long long ud2 = pack2(u4.z, u4.z);
            unsigned long long ud3 = pack2(u4.w, u4.w);
            const ulonglong2* wr = (const ulonglong2*)(wp + c * 64);
            #pragma unroll
            for (int i = 0; i < 4; i++) {
                ulonglong2 wv = wr[i];
                acc[2 * i][0] = ffma2(wv.x, ud0, acc[2 * i][0]);
                acc[2 * i][1] = ffma2(wv.x, ud1, acc[2 * i][1]);
                acc[2 * i][2] = ffma2(wv.x, ud2, acc[2 * i][2]);
                acc[2 * i][3] = ffma2(wv.x, ud3, acc[2 * i][3]);
                acc[2 * i + 1][0] = ffma2(wv.y, ud0, acc[2 * i + 1][0]);
                acc[2 * i + 1][1] = ffma2(wv.y, ud1, acc[2 * i + 1][1]);
                acc[2 * i + 1][2] = ffma2(wv.y, ud2, acc[2 * i + 1][2]);
                acc[2 * i + 1][3] = ffma2(wv.y, ud3, acc[2 * i + 1][3]);
            }
        }
    }
    __syncthreads();

    #pragma unroll
    for (int i = 0; i < 8; i++) {
        int d = d0 + 2 * i;
        float blo = s_B[d], bhi = s_B[d + 1];
        #pragma unroll
        for (int j = 0; j < 4; j++) {
            float lo, hi;
            unpack2(acc[i][j], lo, hi);
            s_u[d * 256 + n0 + j] = fmaxf(lo + blo, 0.f);
            s_u[(d + 1) * 256 + n0 + j] = fmaxf(hi + bhi, 0.f);
        }
    }
    __syncthreads();

    const int e0 = (tid >> 6) * 8;
    unsigned long long acc2[8][2];
    #pragma unroll
    for (int i = 0; i < 8; i++) { acc2[i][0] = 0ull; acc2[i][1] = 0ull; }
    {
        const float* dp = s_u + n0;
        const unsigned long long* wp2 = s_w2d + e0;
        #pragma unroll 2
        for (int d = 0; d < 64; d++) {
            ulonglong2 uu = *(const ulonglong2*)(dp + d * 256);
            const ulonglong2* wd = (const ulonglong2*)(wp2 + d * 32);
            #pragma unroll
            for (int i = 0; i < 4; i++) {
                ulonglong2 wv = wd[i];
                acc2[2 * i][0] = ffma2(wv.x, uu.x, acc2[2 * i][0]);
                acc2[2 * i][1] = ffma2(wv.x, uu.y, acc2[2 * i][1]);
                acc2[2 * i + 1][0] = ffma2(wv.y, uu.x, acc2[2 * i + 1][0]);
                acc2[2 * i + 1][1] = ffma2(wv.y, uu.y, acc2[2 * i + 1][1]);
            }
        }
    }
    __syncthreads();   // all GEMM2 reads of s_u done -> s_u reusable as s_red

    // ---- epilogue: +b2, store, stage per-thread e-max in smem ----
    float* s_red = (float*)dsm;            // [64 ngroups][33 pad] floats (first 32 used)
    const int ngi = tid & 63;
    const int xy = pos0 + (n0 >> 5);
    const int g0 = n0 & 31;
    #pragma unroll
    for (int e = 0; e < 8; e++) {
        float v0, v1, v2, v3;
        unpack2(acc2[e][0], v0, v1);
        unpack2(acc2[e][1], v2, v3);
        float bb = s_b2[e0 + e];
        v0 += bb; v1 += bb; v2 += bb; v3 += bb;
        *(float4*)&out[(((size_t)b * 32 + e0 + e) * 1024 + xy) * 32 + g0] =
            make_float4(v0, v1, v2, v3);
        s_red[ngi * 33 + e0 + e] = fmaxf(fmaxf(v0, v1), fmaxf(v2, v3));
    }
    __syncthreads();
    if (tid < 32) {
        float m = s_red[tid];
        #pragma unroll 8
        for (int k = 1; k < 64; k++) m = fmaxf(m, s_red[k * 33 + tid]);
        atomicMax(&g_ftg[b * 32 + tid], fkey(m));
    }
}

// ---------------- decode ftg keys into the tail of d_out ------------------------
__global__ void k_fin(float* __restrict__ out) {
    int i = threadIdx.x;                  // 256
    unsigned k = g_ftg[i];
    unsigned u = (k & 0x80000000u) ? (k ^ 0x80000000u) : ~k;
    out[(size_t)NB * 32 * 1024 * 32 + i] = __uint_as_float(u);
}

// ---------------- launch --------------------------------------------------------
#define SMEM_C1 ((8 * 4 * 40 + 72 * 32) * 4)

extern "C" void kernel_launch(void* const* d_in, const int* in_sizes, int n_in,
                              void* d_out, int out_size) {
    const float* pts   = (const float*)d_in[0];
    const float* scale = (const float*)d_in[1];
    const float* sigma = (const float*)d_in[2];
    const float* A     = (const float*)d_in[3];
    const float* icmp  = (const float*)d_in[4];
    int base = (n_in >= 16) ? 7 : 5;     // skip res_pt/res_r int scalars if present
    const float* Ws1 = (const float*)d_in[base + 0];
    const float* bs1 = (const float*)d_in[base + 1];
    const float* Ws2 = (const float*)d_in[base + 2];
    const float* bs2 = (const float*)d_in[base + 3];
    const float* Wg  = (const float*)d_in[base + 4];
    const float* W1  = (const float*)d_in[base + 5];
    const float* b1  = (const float*)d_in[base + 6];
    const float* W2  = (const float*)d_in[base + 7];
    const float* b2  = (const float*)d_in[base + 8];
    float* out = (float*)d_out;

    float *ftp = nullptr, *h1p = nullptr, *h2p = nullptr, *wc1p = nullptr, *wc2p = nullptr;
    cudaGetSymbolAddress((void**)&ftp, g_ft);
    cudaGetSymbolAddress((void**)&h1p, g_h1);
    cudaGetSymbolAddress((void**)&h2p, g_h2);
    cudaGetSymbolAddress((void**)&wc1p, g_wc1);
    cudaGetSymbolAddress((void**)&wc2p, g_wc2);

    static int attr_done = 0;
    if (!attr_done) {
        cudaFuncSetAttribute(k_main, cudaFuncAttributeMaxDynamicSharedMemorySize, SMEM_MAIN);
        cudaFuncSetAttribute(k_conv2w, cudaFuncAttributeMaxDynamicSharedMemorySize, SMEM_C2W);
        attr_done = 1;
    }

    k_init<<<72, 256>>>(Ws1, Ws2, W1, W2, Wg);
    k_scatter<<<(NB * NPT + 255) / 256, 256>>>(pts, scale, sigma, A, icmp);
    // conv1: 8->32, ROWS=2, CPT=2, NGRP=32 -> 256 threads, grid (16,1,8) = 128 blocks
    k_cgemm<8, 32, 32, 2, 32, 2><<<dim3(16, 1, 8), 256, SMEM_C1>>>(ftp, wc1p, bs1, h1p);
    // conv2 (+fused ftmax partials): grid (16,8) = 128 blocks x 256 threads
    k_conv2w<<<dim3(16, 8), 256, SMEM_C2W>>>(h1p, wc2p, bs2, h2p);
    // head prep: 8 blocks (one per b) x 64 threads
    k_head<<<NB, 64>>>(W1, b1);
    // head GEMMs + fused ft_g max: grid (128, 8) x 256 threads
    k_main<<<dim3(128, NB), 256, SMEM_MAIN>>>(Wg, b2, out);
    // decode ft_g keys
    k_fin<<<1, 256>>>(out);
}